// round 3
// baseline (speedup 1.0000x reference)
#include <cuda_runtime.h>
#include <cuda_bf16.h>
#include <cstdint>

#define NN   10000
#define EE   320000
#define GG   64
#define NIN  64
#define EIN  16
#define HID  256

// ---------------- scratch (__device__ globals; no allocation allowed) ----------------
__device__ __align__(16) float g_W0f[HID * NIN];   // we2 @ l0_lw
__device__ __align__(16) float g_b0f[NIN];         // be2 @ l0_lw + l0_lb
__device__ __align__(16) float g_W1f[HID * HID];   // we2 @ l1_lw
__device__ __align__(16) float g_b1f[HID];         // be2 @ l1_lw + l1_lb
__device__ __align__(16) float g_agg0[NN * NIN];
__device__ __align__(16) float g_agg1[NN * HID];
__device__ __align__(16) float g_x1[NN * HID];
__device__ __align__(16) float g_tmp[NN * HID];
__device__ __align__(16) float g_x2[NN * HID];
__device__ float g_cnt[GG];

// ---------------- weight pre-products: W{0,1}f = we2 @ l{0,1}_lw (+ fused biases) ----
__global__ void fuse_weights(const float* __restrict__ we2, const float* __restrict__ be2,
                             const float* __restrict__ l0_lw, const float* __restrict__ l0_lb,
                             const float* __restrict__ l1_lw, const float* __restrict__ l1_lb) {
    __shared__ float s_w[HID];
    int k = blockIdx.x;      // hidden row of we2
    int n = threadIdx.x;     // output col
    s_w[n] = we2[k * HID + n];
    __syncthreads();
    float acc = 0.f;
    for (int j = 0; j < HID; j++) acc += s_w[j] * l1_lw[j * HID + n];
    g_W1f[k * HID + n] = acc;
    if (n < NIN) {
        float a0 = 0.f;
        for (int j = 0; j < HID; j++) a0 += s_w[j] * l0_lw[j * NIN + n];
        g_W0f[k * NIN + n] = a0;
    }
    if (k == 0) {
        float bb = 0.f;
        for (int j = 0; j < HID; j++) bb += be2[j] * l1_lw[j * HID + n];
        g_b1f[n] = bb + l1_lb[n];
        if (n < NIN) {
            float b0 = 0.f;
            for (int j = 0; j < HID; j++) b0 += be2[j] * l0_lw[j * NIN + n];
            g_b0f[n] = b0 + l0_lb[n];
        }
    }
}

__global__ void zero_aggs() {
    int i = blockIdx.x * 256 + threadIdx.x;
    int st = gridDim.x * 256;
    for (int j = i; j < NN * HID; j += st) g_agg1[j] = 0.f;
    for (int j = i; j < NN * NIN; j += st) g_agg0[j] = 0.f;
}

// ---------------- fused edge kernel -------------------------------------------------
// For a 64-edge tile: recompute hidden = ReLU(ea@we1+be1) chunk-by-chunk in SMEM,
// GEMM against fused weight, then epilogue: msg = ReLU(x[src] + eproj + bias),
// atomicAdd into agg[dst]. CONV=0: CIN=64 (TN=64); CONV=1: CIN=256 (TN=128, grid.y=2).
template <int CONV>
__global__ void __launch_bounds__(256) edge_conv(
    const float* __restrict__ ea, const int* __restrict__ src,
    const int* __restrict__ dst, const float* __restrict__ we1,
    const float* __restrict__ be1, const float* __restrict__ xin_param) {
    constexpr int CIN = CONV ? HID : NIN;
    constexpr int TN  = CONV ? 128 : 64;
    constexpr int TE = 64, KC = 32, NI = TN / 32;
    const float* Wf  = CONV ? g_W1f : g_W0f;
    const float* bf  = CONV ? g_b1f : g_b0f;
    const float* xp  = CONV ? g_x1 : xin_param;
    float* agg       = CONV ? g_agg1 : g_agg0;

    __shared__ __align__(16) float s_ea[TE][EIN];      // edge_attr tile
    __shared__ __align__(16) float s_we1[EIN][HID];    // full first-layer weight
    __shared__ float s_A[KC][TE + 1];                  // hidden chunk (relu'd)
    __shared__ __align__(16) float s_B[KC][TN];        // fused weight chunk
    __shared__ int s_src[TE], s_dst[TE];

    const int tid = threadIdx.x, cx = tid & 31, cy = tid >> 5;
    const int e0 = blockIdx.x * TE, n0 = blockIdx.y * TN;

    // loads: ea tile (1024 floats) and we1 (4096 floats), vectorized
    reinterpret_cast<float4*>(&s_ea[0][0])[tid] =
        reinterpret_cast<const float4*>(ea + (size_t)e0 * EIN)[tid];
#pragma unroll
    for (int i = tid; i < EIN * HID / 4; i += 256)
        reinterpret_cast<float4*>(&s_we1[0][0])[i] =
            reinterpret_cast<const float4*>(we1)[i];
    if (tid < TE) {
        s_src[tid] = src[e0 + tid];
        s_dst[tid] = dst[e0 + tid];
    }

    float acc[8][NI];
#pragma unroll
    for (int j = 0; j < 8; j++)
#pragma unroll
        for (int i = 0; i < NI; i++) acc[j][i] = 0.f;

    for (int kc = 0; kc < HID; kc += KC) {
        __syncthreads();  // prior reads of s_A/s_B done; initial loads visible
        // load fused-weight chunk [KC][TN]
#pragma unroll
        for (int i = tid; i < KC * TN / 4; i += 256) {
            int k = i / (TN / 4), nq = i % (TN / 4);
            reinterpret_cast<float4*>(&s_B[k][0])[nq] =
                reinterpret_cast<const float4*>(Wf + (size_t)(kc + k) * CIN + n0)[nq];
        }
        // compute hidden chunk A[kk][e] = relu(ea@we1 + be1), kk = cx, e = cy*8+j
        float bb = be1[kc + cx];
#pragma unroll
        for (int j = 0; j < 8; j++) {
            int e = cy * 8 + j;
            float v = bb;
#pragma unroll
            for (int k = 0; k < EIN; k++) v += s_ea[e][k] * s_we1[k][kc + cx];
            s_A[cx][e] = fmaxf(v, 0.f);
        }
        __syncthreads();
        // main GEMM: thread covers 8 edges x NI cols (cols = cx + 32*i, contiguous per instr)
#pragma unroll
        for (int k = 0; k < KC; k++) {
            float b[NI];
#pragma unroll
            for (int i = 0; i < NI; i++) b[i] = s_B[k][cx + 32 * i];
#pragma unroll
            for (int j = 0; j < 8; j++) {
                float a = s_A[k][cy * 8 + j];
#pragma unroll
                for (int i = 0; i < NI; i++) acc[j][i] = fmaf(a, b[i], acc[j][i]);
            }
        }
    }

    // epilogue: gather x[src], relu, scatter-add agg[dst] (lane-contiguous atomics)
    float bias[NI];
#pragma unroll
    for (int i = 0; i < NI; i++) bias[i] = bf[n0 + cx + 32 * i];
#pragma unroll
    for (int j = 0; j < 8; j++) {
        int e = cy * 8 + j;
        int s = s_src[e], d = s_dst[e];
        const float* xr = xp + (size_t)s * CIN + n0;
        float* ar = agg + (size_t)d * CIN + n0;
#pragma unroll
        for (int i = 0; i < NI; i++) {
            int n = cx + 32 * i;
            float m = fmaxf(acc[j][i] + bias[i] + xr[n], 0.f);
            atomicAdd(ar + n, m);
        }
    }
}

// ---------------- node MLP GEMM: out = relu((A1[+A2]) @ W + b) -----------------------
// SEL 0: (x + agg0) @ l0_w1 -> g_tmp      SEL 1: g_tmp @ l0_w2 -> g_x1
// SEL 2: (x1 + agg1) @ l1_w1 -> g_tmp     SEL 3: g_tmp @ l1_w2 -> g_x2
template <int K, int SEL>
__global__ void __launch_bounds__(256) node_mlp(const float* __restrict__ xin_param,
                                                const float* __restrict__ W,
                                                const float* __restrict__ b) {
    constexpr int TM = 64, TN = 128, KC = 32;
    constexpr bool HAS2 = (SEL == 0 || SEL == 2);
    const float* A1 = (SEL == 0) ? xin_param : (SEL == 2 ? g_x1 : g_tmp);
    const float* A2 = (SEL == 0) ? g_agg0 : g_agg1;  // used only when HAS2
    float* out = (SEL == 0 || SEL == 2) ? g_tmp : (SEL == 1 ? g_x1 : g_x2);

    __shared__ float s_A[KC][TM + 1];
    __shared__ __align__(16) float s_B[KC][TN];
    int tid = threadIdx.x, cx = tid & 31, cy = tid >> 5;
    int m0 = blockIdx.x * TM, n0 = blockIdx.y * TN;
    float acc[8][4] = {};

    for (int kc = 0; kc < K; kc += KC) {
        __syncthreads();
        for (int i = tid; i < KC * TM; i += 256) {
            int k = i % KC, m = i / KC, gm = m0 + m;
            float v = 0.f;
            if (gm < NN) {
                v = A1[(size_t)gm * K + kc + k];
                if constexpr (HAS2) v += A2[(size_t)gm * K + kc + k];
            }
            s_A[k][m] = v;
        }
        for (int i = tid; i < KC * TN / 4; i += 256) {
            int k = i / (TN / 4), nq = i % (TN / 4);
            reinterpret_cast<float4*>(&s_B[k][0])[nq] =
                reinterpret_cast<const float4*>(W + (size_t)(kc + k) * HID + n0)[nq];
        }
        __syncthreads();
#pragma unroll
        for (int k = 0; k < KC; k++) {
            float bb[4];
#pragma unroll
            for (int i = 0; i < 4; i++) bb[i] = s_B[k][cx + 32 * i];
#pragma unroll
            for (int j = 0; j < 8; j++) {
                float a = s_A[k][cy * 8 + j];
#pragma unroll
                for (int i = 0; i < 4; i++) acc[j][i] = fmaf(a, bb[i], acc[j][i]);
            }
        }
    }
#pragma unroll
    for (int j = 0; j < 8; j++) {
        int m = m0 + cy * 8 + j;
        if (m < NN) {
#pragma unroll
            for (int i = 0; i < 4; i++) {
                int n = n0 + cx + 32 * i;
                out[(size_t)m * HID + n] = fmaxf(acc[j][i] + b[n], 0.f);
            }
        }
    }
}

// ---------------- pooling ------------------------------------------------------------
__global__ void zero_out(float* out) {
    int i = blockIdx.x * 256 + threadIdx.x;
    if (i < GG * HID) out[i] = 0.f;
    if (i < GG) g_cnt[i] = 0.f;
}
__global__ void pool_count(const int* __restrict__ batch) {
    int i = blockIdx.x * 256 + threadIdx.x;
    if (i < NN) atomicAdd(&g_cnt[batch[i]], 1.f);
}
__global__ void pool_accum(const int* __restrict__ batch, float* out) {
    int c = threadIdx.x;        // 256 channels
    int nb = blockIdx.x * 8;
#pragma unroll
    for (int j = 0; j < 8; j++) {
        int node = nb + j;
        if (node < NN) {
            int g = batch[node];
            atomicAdd(&out[g * HID + c], g_x2[(size_t)node * HID + c]);
        }
    }
}
__global__ void pool_div(float* out) {
    int i = blockIdx.x * 256 + threadIdx.x;
    if (i < GG * HID) out[i] /= fmaxf(g_cnt[i / HID], 1.f);
}

// ---------------- launch -------------------------------------------------------------
extern "C" void kernel_launch(void* const* d_in, const int* in_sizes, int n_in,
                              void* d_out, int out_size) {
    const float* x     = (const float*)d_in[0];
    const float* ea    = (const float*)d_in[1];
    const int*   eidx  = (const int*)d_in[2];   // [2, E] int32 (JAX x64 disabled)
    const int*   batch = (const int*)d_in[3];
    const float* we1 = (const float*)d_in[4];
    const float* be1 = (const float*)d_in[5];
    const float* we2 = (const float*)d_in[6];
    const float* be2 = (const float*)d_in[7];
    const float* l0_lw = (const float*)d_in[8];
    const float* l0_lb = (const float*)d_in[9];
    const float* l0_w1 = (const float*)d_in[10];
    const float* l0_b1 = (const float*)d_in[11];
    const float* l0_w2 = (const float*)d_in[12];
    const float* l0_b2 = (const float*)d_in[13];
    const float* l1_lw = (const float*)d_in[14];
    const float* l1_lb = (const float*)d_in[15];
    const float* l1_w1 = (const float*)d_in[16];
    const float* l1_b1 = (const float*)d_in[17];
    const float* l1_w2 = (const float*)d_in[18];
    const float* l1_b2 = (const float*)d_in[19];
    const int* src = eidx;
    const int* dst = eidx + EE;
    float* out = (float*)d_out;

    fuse_weights<<<HID, HID>>>(we2, be2, l0_lw, l0_lb, l1_lw, l1_lb);
    zero_aggs<<<2048, 256>>>();

    // conv 0
    edge_conv<0><<<dim3(EE / 64, 1), 256>>>(ea, src, dst, we1, be1, x);
    node_mlp<64, 0><<<dim3((NN + 63) / 64, 2), 256>>>(x, l0_w1, l0_b1);
    node_mlp<256, 1><<<dim3((NN + 63) / 64, 2), 256>>>(nullptr, l0_w2, l0_b2);

    // conv 1
    edge_conv<1><<<dim3(EE / 64, 2), 256>>>(ea, src, dst, we1, be1, nullptr);
    node_mlp<256, 2><<<dim3((NN + 63) / 64, 2), 256>>>(nullptr, l1_w1, l1_b1);
    node_mlp<256, 3><<<dim3((NN + 63) / 64, 2), 256>>>(nullptr, l1_w2, l1_b2);

    // mean pool per graph
    zero_out<<<64, 256>>>(out);
    pool_count<<<(NN + 255) / 256, 256>>>(batch);
    pool_accum<<<(NN + 7) / 8, 256>>>(batch, out);
    pool_div<<<(GG * HID + 255) / 256, 256>>>(out);
}

// round 6
// speedup vs baseline: 1.0205x; 1.0205x over previous
#include <cuda_runtime.h>
#include <cuda_bf16.h>
#include <cstdint>

#define NN   10000
#define EE   320000
#define GG   64
#define NIN  64
#define EIN  16
#define HID  256

// ---------------- packed f32x2 helpers (sm_100a: SASS FFMA2) -------------------------
__device__ __forceinline__ unsigned long long bcast2(float v) {
    unsigned long long r;
    asm("mov.b64 %0, {%1, %1};" : "=l"(r) : "f"(v));
    return r;
}
__device__ __forceinline__ unsigned long long pack2f(float lo, float hi) {
    unsigned long long r;
    asm("mov.b64 %0, {%1, %2};" : "=l"(r) : "f"(lo), "f"(hi));
    return r;
}
__device__ __forceinline__ void unpack2(unsigned long long v, float& lo, float& hi) {
    asm("mov.b64 {%0, %1}, %2;" : "=f"(lo), "=f"(hi) : "l"(v));
}
__device__ __forceinline__ unsigned long long fma2(unsigned long long a,
                                                   unsigned long long b,
                                                   unsigned long long c) {
    unsigned long long d;
    asm("fma.rn.f32x2 %0, %1, %2, %3;" : "=l"(d) : "l"(a), "l"(b), "l"(c));
    return d;
}

// ---------------- scratch (__device__ globals; no allocation allowed) ----------------
__device__ __align__(16) float g_W0f[HID * NIN];   // we2 @ l0_lw
__device__ __align__(16) float g_b0f[NIN];         // be2 @ l0_lw + l0_lb
__device__ __align__(16) float g_W1f[HID * HID];   // we2 @ l1_lw
__device__ __align__(16) float g_b1f[HID];         // be2 @ l1_lw + l1_lb
__device__ __align__(16) float g_agg0[NN * NIN];
__device__ __align__(16) float g_agg1[NN * HID];
__device__ __align__(16) float g_x1[NN * HID];
__device__ __align__(16) float g_tmp[NN * HID];
__device__ __align__(16) float g_x2[NN * HID];
__device__ float g_cnt[GG];

// ---------------- weight pre-products: W{0,1}f = we2 @ l{0,1}_lw (+ fused biases) ----
__global__ void fuse_weights(const float* __restrict__ we2, const float* __restrict__ be2,
                             const float* __restrict__ l0_lw, const float* __restrict__ l0_lb,
                             const float* __restrict__ l1_lw, const float* __restrict__ l1_lb) {
    __shared__ float s_w[HID];
    int k = blockIdx.x;      // hidden row of we2
    int n = threadIdx.x;     // output col
    s_w[n] = we2[k * HID + n];
    __syncthreads();
    float acc = 0.f;
    for (int j = 0; j < HID; j++) acc += s_w[j] * l1_lw[j * HID + n];
    g_W1f[k * HID + n] = acc;
    if (n < NIN) {
        float a0 = 0.f;
        for (int j = 0; j < HID; j++) a0 += s_w[j] * l0_lw[j * NIN + n];
        g_W0f[k * NIN + n] = a0;
    }
    if (k == 0) {
        float bb = 0.f;
        for (int j = 0; j < HID; j++) bb += be2[j] * l1_lw[j * HID + n];
        g_b1f[n] = bb + l1_lb[n];
        if (n < NIN) {
            float b0 = 0.f;
            for (int j = 0; j < HID; j++) b0 += be2[j] * l0_lw[j * NIN + n];
            g_b0f[n] = b0 + l0_lb[n];
        }
    }
}

__global__ void zero_aggs() {
    int i = blockIdx.x * 256 + threadIdx.x;
    int st = gridDim.x * 256;
    for (int j = i; j < NN * HID; j += st) g_agg1[j] = 0.f;
    for (int j = i; j < NN * NIN; j += st) g_agg0[j] = 0.f;
}

// ---------------- fused edge kernel -------------------------------------------------
// 64-edge tile: recompute hidden = ReLU(ea@we1+be1) chunk-by-chunk in SMEM (f32x2
// packed along K), packed-GEMM against fused weight (f32x2 along edge pairs), then
// epilogue: msg = ReLU(x[src] + eproj + bias), atomicAdd into agg[dst].
template <int CONV>
__global__ void __launch_bounds__(256) edge_conv(
    const float* __restrict__ ea, const int* __restrict__ src,
    const int* __restrict__ dst, const float* __restrict__ we1,
    const float* __restrict__ be1, const float* __restrict__ xin_param) {
    constexpr int CIN = CONV ? HID : NIN;
    constexpr int TN  = CONV ? 128 : 64;
    constexpr int TE = 64, KC = 32, NI = TN / 32;
    const float* Wf  = CONV ? g_W1f : g_W0f;
    const float* bf  = CONV ? g_b1f : g_b0f;
    const float* xp  = CONV ? g_x1 : xin_param;
    float* agg       = CONV ? g_agg1 : g_agg0;

    __shared__ __align__(16) float s_ea[TE][EIN];      // edge_attr tile (row = 64B)
    __shared__ __align__(16) float s_we1[EIN][HID];    // full first-layer weight
    __shared__ __align__(16) float s_A[KC][TE + 2];    // hidden chunk (stride 66 -> 8B-aligned rows)
    __shared__ __align__(16) float s_B[KC][TN];        // fused weight chunk
    __shared__ int s_src[TE], s_dst[TE];

    const int tid = threadIdx.x, cx = tid & 31, cy = tid >> 5;
    const int e0 = blockIdx.x * TE, n0 = blockIdx.y * TN;

    reinterpret_cast<float4*>(&s_ea[0][0])[tid] =
        reinterpret_cast<const float4*>(ea + (size_t)e0 * EIN)[tid];
#pragma unroll
    for (int i = tid; i < EIN * HID / 4; i += 256)
        reinterpret_cast<float4*>(&s_we1[0][0])[i] =
            reinterpret_cast<const float4*>(we1)[i];
    if (tid < TE) {
        s_src[tid] = src[e0 + tid];
        s_dst[tid] = dst[e0 + tid];
    }

    unsigned long long acc2[4][NI];
#pragma unroll
    for (int p = 0; p < 4; p++)
#pragma unroll
        for (int i = 0; i < NI; i++) acc2[p][i] = 0ULL;

    for (int kc = 0; kc < HID; kc += KC) {
        __syncthreads();  // prior reads of s_A/s_B done; initial loads visible
        // load fused-weight chunk [KC][TN]
#pragma unroll
        for (int i = tid; i < KC * TN / 4; i += 256) {
            int k = i / (TN / 4), nq = i % (TN / 4);
            reinterpret_cast<float4*>(&s_B[k][0])[nq] =
                reinterpret_cast<const float4*>(Wf + (size_t)(kc + k) * CIN + n0)[nq];
        }
        // hidden chunk A[kk][e] = relu(ea@we1 + be1), kk = cx, e = cy*8+j
        // packed along K: ea pairs contiguous (LDS.64), we1 pairs packed per thread
        {
            float bb = be1[kc + cx];
            unsigned long long w2[EIN / 2];
#pragma unroll
            for (int k = 0; k < EIN; k += 2)
                w2[k / 2] = pack2f(s_we1[k][kc + cx], s_we1[k + 1][kc + cx]);
#pragma unroll
            for (int j = 0; j < 8; j++) {
                int e = cy * 8 + j;
                const unsigned long long* earow =
                    reinterpret_cast<const unsigned long long*>(&s_ea[e][0]);
                unsigned long long v2 = 0ULL;
#pragma unroll
                for (int k = 0; k < EIN / 2; k++) v2 = fma2(earow[k], w2[k], v2);
                float lo, hi;
                unpack2(v2, lo, hi);
                s_A[cx][e] = fmaxf(lo + hi + bb, 0.f);
            }
        }
        __syncthreads();
        // main GEMM (packed over edge pairs): 4*NI FFMA2 per k
#pragma unroll
        for (int k = 0; k < KC; k++) {
            unsigned long long b2[NI];
#pragma unroll
            for (int i = 0; i < NI; i++) b2[i] = bcast2(s_B[k][cx + 32 * i]);
            const unsigned long long* arow =
                reinterpret_cast<const unsigned long long*>(&s_A[k][cy * 8]);
#pragma unroll
            for (int p = 0; p < 4; p++) {
                unsigned long long a2 = arow[p];
#pragma unroll
                for (int i = 0; i < NI; i++) acc2[p][i] = fma2(a2, b2[i], acc2[p][i]);
            }
        }
    }

    // epilogue: gather x[src], relu, scatter-add agg[dst] (lane-contiguous atomics)
    float bias[NI];
#pragma unroll
    for (int i = 0; i < NI; i++) bias[i] = bf[n0 + cx + 32 * i];
#pragma unroll
    for (int p = 0; p < 4; p++) {
        int ea0 = cy * 8 + 2 * p;
        int s0 = s_src[ea0], d0 = s_dst[ea0];
        int s1 = s_src[ea0 + 1], d1 = s_dst[ea0 + 1];
        const float* xr0 = xp + (size_t)s0 * CIN + n0;
        const float* xr1 = xp + (size_t)s1 * CIN + n0;
        float* ar0 = agg + (size_t)d0 * CIN + n0;
        float* ar1 = agg + (size_t)d1 * CIN + n0;
#pragma unroll
        for (int i = 0; i < NI; i++) {
            int n = cx + 32 * i;
            float lo, hi;
            unpack2(acc2[p][i], lo, hi);
            atomicAdd(ar0 + n, fmaxf(lo + bias[i] + xr0[n], 0.f));
            atomicAdd(ar1 + n, fmaxf(hi + bias[i] + xr1[n], 0.f));
        }
    }
}

// ---------------- node MLP GEMM: out = relu((A1[+A2]) @ W + b) -----------------------
// SEL 0: (x + agg0) @ l0_w1 -> g_tmp      SEL 1: g_tmp @ l0_w2 -> g_x1
// SEL 2: (x1 + agg1) @ l1_w1 -> g_tmp     SEL 3: g_tmp @ l1_w2 -> g_x2
template <int K, int SEL>
__global__ void __launch_bounds__(256) node_mlp(const float* __restrict__ xin_param,
                                                const float* __restrict__ W,
                                                const float* __restrict__ b) {
    constexpr int TM = 64, TN = 128, KC = 32;
    constexpr bool HAS2 = (SEL == 0 || SEL == 2);
    const float* A1 = (SEL == 0) ? xin_param : (SEL == 2 ? g_x1 : g_tmp);
    const float* A2 = (SEL == 0) ? g_agg0 : g_agg1;  // used only when HAS2
    float* out = (SEL == 0 || SEL == 2) ? g_tmp : (SEL == 1 ? g_x1 : g_x2);

    __shared__ __align__(16) float s_A[KC][TM + 2];
    __shared__ __align__(16) float s_B[KC][TN];
    int tid = threadIdx.x, cx = tid & 31, cy = tid >> 5;
    int m0 = blockIdx.x * TM, n0 = blockIdx.y * TN;
    unsigned long long acc2[4][4];
#pragma unroll
    for (int p = 0; p < 4; p++)
#pragma unroll
        for (int i = 0; i < 4; i++) acc2[p][i] = 0ULL;

    for (int kc = 0; kc < K; kc += KC) {
        __syncthreads();
        for (int i = tid; i < KC * TM; i += 256) {
            int k = i % KC, m = i / KC, gm = m0 + m;
            float v = 0.f;
            if (gm < NN) {
                v = A1[(size_t)gm * K + kc + k];
                if constexpr (HAS2) v += A2[(size_t)gm * K + kc + k];
            }
            s_A[k][m] = v;
        }
        for (int i = tid; i < KC * TN / 4; i += 256) {
            int k = i / (TN / 4), nq = i % (TN / 4);
            reinterpret_cast<float4*>(&s_B[k][0])[nq] =
                reinterpret_cast<const float4*>(W + (size_t)(kc + k) * HID + n0)[nq];
        }
        __syncthreads();
#pragma unroll
        for (int k = 0; k < KC; k++) {
            unsigned long long b2[4];
#pragma unroll
            for (int i = 0; i < 4; i++) b2[i] = bcast2(s_B[k][cx + 32 * i]);
            const unsigned long long* arow =
                reinterpret_cast<const unsigned long long*>(&s_A[k][cy * 8]);
#pragma unroll
            for (int p = 0; p < 4; p++) {
                unsigned long long a2 = arow[p];
#pragma unroll
                for (int i = 0; i < 4; i++) acc2[p][i] = fma2(a2, b2[i], acc2[p][i]);
            }
        }
    }
#pragma unroll
    for (int p = 0; p < 4; p++) {
        int mA = m0 + cy * 8 + 2 * p;
        int mB = mA + 1;
#pragma unroll
        for (int i = 0; i < 4; i++) {
            int n = n0 + cx + 32 * i;
            float lo, hi;
            unpack2(acc2[p][i], lo, hi);
            if (mA < NN) out[(size_t)mA * HID + n] = fmaxf(lo + b[n], 0.f);
            if (mB < NN) out[(size_t)mB * HID + n] = fmaxf(hi + b[n], 0.f);
        }
    }
}

// ---------------- pooling ------------------------------------------------------------
__global__ void zero_out(float* out) {
    int i = blockIdx.x * 256 + threadIdx.x;
    if (i < GG * HID) out[i] = 0.f;
    if (i < GG) g_cnt[i] = 0.f;
}
__global__ void pool_count(const int* __restrict__ batch) {
    int i = blockIdx.x * 256 + threadIdx.x;
    if (i < NN) atomicAdd(&g_cnt[batch[i]], 1.f);
}
__global__ void pool_accum(const int* __restrict__ batch, float* out) {
    int c = threadIdx.x;        // 256 channels
    int nb = blockIdx.x * 8;
#pragma unroll
    for (int j = 0; j < 8; j++) {
        int node = nb + j;
        if (node < NN) {
            int g = batch[node];
            atomicAdd(&out[g * HID + c], g_x2[(size_t)node * HID + c]);
        }
    }
}
__global__ void pool_div(float* out) {
    int i = blockIdx.x * 256 + threadIdx.x;
    if (i < GG * HID) out[i] /= fmaxf(g_cnt[i / HID], 1.f);
}

// ---------------- launch -------------------------------------------------------------
extern "C" void kernel_launch(void* const* d_in, const int* in_sizes, int n_in,
                              void* d_out, int out_size) {
    const float* x     = (const float*)d_in[0];
    const float* ea    = (const float*)d_in[1];
    const int*   eidx  = (const int*)d_in[2];   // [2, E] int32 (JAX x64 disabled)
    const int*   batch = (const int*)d_in[3];
    const float* we1 = (const float*)d_in[4];
    const float* be1 = (const float*)d_in[5];
    const float* we2 = (const float*)d_in[6];
    const float* be2 = (const float*)d_in[7];
    const float* l0_lw = (const float*)d_in[8];
    const float* l0_lb = (const float*)d_in[9];
    const float* l0_w1 = (const float*)d_in[10];
    const float* l0_b1 = (const float*)d_in[11];
    const float* l0_w2 = (const float*)d_in[12];
    const float* l0_b2 = (const float*)d_in[13];
    const float* l1_lw = (const float*)d_in[14];
    const float* l1_lb = (const float*)d_in[15];
    const float* l1_w1 = (const float*)d_in[16];
    const float* l1_b1 = (const float*)d_in[17];
    const float* l1_w2 = (const float*)d_in[18];
    const float* l1_b2 = (const float*)d_in[19];
    const int* src = eidx;
    const int* dst = eidx + EE;
    float* out = (float*)d_out;

    fuse_weights<<<HID, HID>>>(we2, be2, l0_lw, l0_lb, l1_lw, l1_lb);
    zero_aggs<<<2048, 256>>>();

    // conv 0
    edge_conv<0><<<dim3(EE / 64, 1), 256>>>(ea, src, dst, we1, be1, x);
    node_mlp<64, 0><<<dim3((NN + 63) / 64, 2), 256>>>(x, l0_w1, l0_b1);
    node_mlp<256, 1><<<dim3((NN + 63) / 64, 2), 256>>>(nullptr, l0_w2, l0_b2);

    // conv 1
    edge_conv<1><<<dim3(EE / 64, 2), 256>>>(ea, src, dst, we1, be1, nullptr);
    node_mlp<256, 2><<<dim3((NN + 63) / 64, 2), 256>>>(nullptr, l1_w1, l1_b1);
    node_mlp<256, 3><<<dim3((NN + 63) / 64, 2), 256>>>(nullptr, l1_w2, l1_b2);

    // mean pool per graph
    zero_out<<<64, 256>>>(out);
    pool_count<<<(NN + 255) / 256, 256>>>(batch);
    pool_accum<<<(NN + 7) / 8, 256>>>(batch, out);
    pool_div<<<(GG * HID + 255) / 256, 256>>>(out);
}